// round 14
// baseline (speedup 1.0000x reference)
#include <cuda_runtime.h>
#include <cuda_bf16.h>
#include <cstdint>

#define B_  4
#define H_  8
#define LQ_ 256
#define LK_ 256
#define DK_ 64
#define BH_ (B_*H_)                 // 32
#define LOG2E 1.4426950408889634f

// ---------------- packed-math helpers -------------------------------------
// f16x2 pack: first PTX operand -> HIGH half
__device__ __forceinline__ uint32_t cvt_h2(float hi, float lo) {
    uint32_t r; asm("cvt.rn.f16x2.f32 %0,%1,%2;" : "=r"(r) : "f"(hi), "f"(lo)); return r;
}
__device__ __forceinline__ uint32_t hadd2(uint32_t a, uint32_t b) {
    uint32_t r; asm("add.rn.f16x2 %0,%1,%2;" : "=r"(r) : "r"(a), "r"(b)); return r;
}
__device__ __forceinline__ uint32_t hfma2(uint32_t a, uint32_t b, uint32_t c) {
    uint32_t r; asm("fma.rn.f16x2 %0,%1,%2,%3;" : "=r"(r) : "r"(a), "r"(b), "r"(c)); return r;
}
__device__ __forceinline__ uint32_t tanh2(uint32_t x) {
    uint32_t y; asm("tanh.approx.f16x2 %0,%1;" : "=r"(y) : "r"(x)); return y;
}
__device__ __forceinline__ void h2tof(uint32_t h, float& lo, float& hi) {
    asm("{.reg .b16 l,h; mov.b32 {l,h},%2; cvt.f32.f16 %0,l; cvt.f32.f16 %1,h;}"
        : "=f"(lo), "=f"(hi) : "r"(h));
}
__device__ __forceinline__ float ex2_fast(float x) {
    float y; asm("ex2.approx.f32 %0,%1;" : "=f"(y) : "f"(x)); return y;
}
__device__ __forceinline__ uint32_t smem_u32(const void* p) {
    return (uint32_t)__cvta_generic_to_shared(p);
}
__device__ __forceinline__ void mma16816(float& c0, float& c1, float& c2, float& c3,
                                         uint32_t a0, uint32_t a1, uint32_t a2, uint32_t a3,
                                         uint32_t b0, uint32_t b1) {
    asm volatile("mma.sync.aligned.m16n8k16.row.col.f32.f16.f16.f32 "
                 "{%0,%1,%2,%3},{%4,%5,%6,%7},{%8,%9},{%0,%1,%2,%3};"
                 : "+f"(c0), "+f"(c1), "+f"(c2), "+f"(c3)
                 : "r"(a0), "r"(a1), "r"(a2), "r"(a3), "r"(b0), "r"(b1));
}

// ---------------------------------------------------------------------------
// ONE fused kernel: in-CTA projections (HMMA, fragments built by direct LDG)
// + additive-attention scores + softmax + HMMA epilogue.
// grid = 512 CTAs (32 bh x 16 q-tiles of 16 rows), 256 thr, 4 CTAs/SM.
// ---------------------------------------------------------------------------
// smem layout (u32 word indices) — identical footprint to R9 (56704 B)
#define SM_KV    0        // 9216: kp f16x2 pitch 32 (proj output); later v f16 pitch 36
#define SM_W2H   9216     // 32
#define SM_S     9248     // 4352 f32 scores pitch 17; later p_h f16 pitch 264
#define SM_PMAX  13600    // 16 x 17  (overlaid by qp_tmp 512 w during proj)
#define SM_PSUM  13872    // 16 x 17
#define SM_M     14144    // 16
#define SM_R     14160    // 16
#define SM_WORDS 14176    // 56704 bytes

#define SM_QPT   13600    // qp_tmp: 16 rows x 32 words (dead before pmax/psum used)

#define P_PITCH_W 132     // p_h pitch in u32 words (264 f16, 528B)
#define V_PITCH_W 36      // v_h pitch in u32 words (72 f16, 144B)

__global__ __launch_bounds__(256, 4) void attn_fused_kernel(
    const float* __restrict__ qg,
    const float* __restrict__ kg,
    const float* __restrict__ v,
    const float* __restrict__ Wq, const float* __restrict__ bq,
    const float* __restrict__ Wk, const float* __restrict__ bk,
    const float* __restrict__ vs_w,
    float* __restrict__ out,        // [BH,256,64]
    float* __restrict__ attn_out)   // [BH,256,256]
{
    extern __shared__ float sm[];
    uint32_t* kv_u   = (uint32_t*)sm + SM_KV;
    uint32_t* w2h_s  = (uint32_t*)sm + SM_W2H;
    float*    s_s    = sm + SM_S;
    uint32_t* ph_u   = (uint32_t*)sm + SM_S;    // overlays s_s after scores die
    uint32_t* qp_tmp = (uint32_t*)sm + SM_QPT;  // proj-phase only
    float* pmax = sm + SM_PMAX;
    float* psum = sm + SM_PSUM;
    float* m_s  = sm + SM_M;
    float* r_s  = sm + SM_R;

    const int tid  = threadIdx.x;
    const int wid  = tid >> 5;
    const int lane = tid & 31;
    const int bh   = blockIdx.x >> 4;
    const int qt   = blockIdx.x & 15;

    // ============ phase P: in-CTA projections via HMMA =====================
    const int lr = lane >> 2;          // 0..7 (fragment row)
    const int lc = 2 * (lane & 3);     // 0,2,4,6 (fragment col pair)

    // ---- qp: this CTA's 16 q rows; warp wid computes n-chunk [8*wid,8*wid+8)
    {
        const float* qbase = qg + (size_t)(bh * LQ_ + qt * 16) * DK_;
        uint32_t aq[4][4];
#pragma unroll
        for (int ks = 0; ks < 4; ks++) {
            const int c = ks * 16 + lc;
            float2 t0 = *(const float2*)(qbase + lr * DK_ + c);
            float2 t1 = *(const float2*)(qbase + (lr + 8) * DK_ + c);
            float2 t2 = *(const float2*)(qbase + lr * DK_ + c + 8);
            float2 t3 = *(const float2*)(qbase + (lr + 8) * DK_ + c + 8);
            aq[ks][0] = cvt_h2(t0.y, t0.x);
            aq[ks][1] = cvt_h2(t1.y, t1.x);
            aq[ks][2] = cvt_h2(t2.y, t2.x);
            aq[ks][3] = cvt_h2(t3.y, t3.x);
        }
        const int nabs = wid * 8 + lr;          // W row (e-col of qp)
        float c0 = 0.f, c1 = 0.f, c2 = 0.f, c3 = 0.f;
#pragma unroll
        for (int ks = 0; ks < 4; ks++) {
            const int k0 = ks * 16 + lc;
            float2 w0 = *(const float2*)(Wq + nabs * DK_ + k0);
            float2 w1 = *(const float2*)(Wq + nabs * DK_ + k0 + 8);
            mma16816(c0, c1, c2, c3, aq[ks][0], aq[ks][1], aq[ks][2], aq[ks][3],
                     cvt_h2(w0.y, w0.x), cvt_h2(w1.y, w1.x));
        }
        const int cb = wid * 8 + lc;
        const float bl = bq[cb], bh2 = bq[cb + 1];
        qp_tmp[lr * 32 + wid * 4 + (lane & 3)]       = cvt_h2(c1 + bh2, c0 + bl);
        qp_tmp[(lr + 8) * 32 + wid * 4 + (lane & 3)] = cvt_h2(c3 + bh2, c2 + bl);
    }

    // ---- kp: warp wid computes k rows [32*wid, 32*wid+32), all 64 cols -----
    {
        const float* kbase = kg + (size_t)(bh * LK_ + wid * 32) * DK_;
        uint32_t ak[2][4][4];
#pragma unroll
        for (int mt = 0; mt < 2; mt++)
#pragma unroll
            for (int ks = 0; ks < 4; ks++) {
                const int r = mt * 16 + lr;
                const int c = ks * 16 + lc;
                float2 t0 = *(const float2*)(kbase + r * DK_ + c);
                float2 t1 = *(const float2*)(kbase + (r + 8) * DK_ + c);
                float2 t2 = *(const float2*)(kbase + r * DK_ + c + 8);
                float2 t3 = *(const float2*)(kbase + (r + 8) * DK_ + c + 8);
                ak[mt][ks][0] = cvt_h2(t0.y, t0.x);
                ak[mt][ks][1] = cvt_h2(t1.y, t1.x);
                ak[mt][ks][2] = cvt_h2(t2.y, t2.x);
                ak[mt][ks][3] = cvt_h2(t3.y, t3.x);
            }
        const int nabs = 0;  // per-n loop below
        (void)nabs;
#pragma unroll 1
        for (int n = 0; n < 8; n++) {
            const int nr = n * 8 + lr;          // W row (e-col of kp)
            float a0 = 0.f, a1 = 0.f, a2 = 0.f, a3 = 0.f;
            float d0 = 0.f, d1 = 0.f, d2 = 0.f, d3 = 0.f;
#pragma unroll
            for (int ks = 0; ks < 4; ks++) {
                const int k0 = ks * 16 + lc;
                float2 w0 = *(const float2*)(Wk + nr * DK_ + k0);
                float2 w1 = *(const float2*)(Wk + nr * DK_ + k0 + 8);
                const uint32_t b0 = cvt_h2(w0.y, w0.x);
                const uint32_t b1 = cvt_h2(w1.y, w1.x);
                mma16816(a0, a1, a2, a3, ak[0][ks][0], ak[0][ks][1], ak[0][ks][2],
                         ak[0][ks][3], b0, b1);
                mma16816(d0, d1, d2, d3, ak[1][ks][0], ak[1][ks][1], ak[1][ks][2],
                         ak[1][ks][3], b0, b1);
            }
            const int cb = n * 8 + lc;
            const float bl = bk[cb], bh2 = bk[cb + 1];
            const int r0 = wid * 32 + lr;
            kv_u[r0 * 32 + n * 4 + (lane & 3)]        = cvt_h2(a1 + bh2, a0 + bl);
            kv_u[(r0 + 8) * 32 + n * 4 + (lane & 3)]  = cvt_h2(a3 + bh2, a2 + bl);
            kv_u[(r0 + 16) * 32 + n * 4 + (lane & 3)] = cvt_h2(d1 + bh2, d0 + bl);
            kv_u[(r0 + 24) * 32 + n * 4 + (lane & 3)] = cvt_h2(d3 + bh2, d2 + bl);
        }
    }
    if (tid < 32) w2h_s[tid] = cvt_h2(vs_w[2 * tid + 1], vs_w[2 * tid]);
    __syncthreads();

    // ============ phase 1: scores (R9 body, kp from smem) ==================
    const int q    = lane & 15;
    const int kh   = lane >> 4;
    const int kbase2 = wid * 32 + kh * 16;
    float cm = -1e30f;

#pragma unroll 1
    for (int h = 0; h < 2; h++) {
        uint32_t qph[16], wh[16];
        {
            const uint4* qs = (const uint4*)(qp_tmp + q * 32 + h * 16);
#pragma unroll
            for (int j = 0; j < 4; j++) {
                uint4 t = qs[j];
                qph[4*j] = t.x; qph[4*j+1] = t.y; qph[4*j+2] = t.z; qph[4*j+3] = t.w;
            }
        }
#pragma unroll
        for (int j = 0; j < 16; j++) wh[j] = w2h_s[h * 16 + j];

        const uint4* kr = (const uint4*)(kv_u + kbase2 * 32 + h * 16);
        float* srow = s_s + kbase2 * 17 + q;
#pragma unroll 2
        for (int kk = 0; kk < 16; kk++, kr += 8, srow += 17) {
            const uint4 c0 = kr[0], c1 = kr[1], c2 = kr[2], c3 = kr[3];
            uint32_t h0 = 0, h1 = 0, g0 = 0, g1 = 0;
            h0 = hfma2(tanh2(hadd2(qph[0],  c0.x)), wh[0],  h0);
            h1 = hfma2(tanh2(hadd2(qph[1],  c0.y)), wh[1],  h1);
            h0 = hfma2(tanh2(hadd2(qph[2],  c0.z)), wh[2],  h0);
            h1 = hfma2(tanh2(hadd2(qph[3],  c0.w)), wh[3],  h1);
            h0 = hfma2(tanh2(hadd2(qph[4],  c1.x)), wh[4],  h0);
            h1 = hfma2(tanh2(hadd2(qph[5],  c1.y)), wh[5],  h1);
            h0 = hfma2(tanh2(hadd2(qph[6],  c1.z)), wh[6],  h0);
            h1 = hfma2(tanh2(hadd2(qph[7],  c1.w)), wh[7],  h1);
            g0 = hfma2(tanh2(hadd2(qph[8],  c2.x)), wh[8],  g0);
            g1 = hfma2(tanh2(hadd2(qph[9],  c2.y)), wh[9],  g1);
            g0 = hfma2(tanh2(hadd2(qph[10], c2.z)), wh[10], g0);
            g1 = hfma2(tanh2(hadd2(qph[11], c2.w)), wh[11], g1);
            g0 = hfma2(tanh2(hadd2(qph[12], c3.x)), wh[12], g0);
            g1 = hfma2(tanh2(hadd2(qph[13], c3.y)), wh[13], g1);
            g0 = hfma2(tanh2(hadd2(qph[14], c3.z)), wh[14], g0);
            g1 = hfma2(tanh2(hadd2(qph[15], c3.w)), wh[15], g1);
            const uint32_t hs = hadd2(h0, h1);
            const uint32_t gs = hadd2(g0, g1);
            float f0, f1, f2, f3;
            h2tof(hs, f0, f1); h2tof(gs, f2, f3);
            const float part = (f0 + f1) + (f2 + f3);

            if (h == 0) {
                *srow = part;
            } else {
                const float sc = *srow + part;
                *srow = sc;
                cm = fmaxf(cm, sc);
            }
        }
    }
    pmax[q * 17 + wid * 2 + kh] = cm;   // overlays qp_tmp (now dead)
    __syncthreads();

    // ---- phase 2: row max + stage v as f16 (pitch 72 f16, overwrites kp) --
    if (tid < 16) {
        float m = pmax[tid * 17];
#pragma unroll
        for (int i = 1; i < 16; i++) m = fmaxf(m, pmax[tid * 17 + i]);
        m_s[tid] = m;
    }
    {
        const float4* vsrc = (const float4*)(v + (size_t)bh * (LK_ * DK_));
#pragma unroll
        for (int i = 0; i < 16; i++) {
            const int idx = tid + 256 * i;           // 0..4095; k=idx>>4, c=idx&15
            float4 t = vsrc[idx];
            const int kk2 = idx >> 4, c = idx & 15;
            uint32_t w0 = cvt_h2(t.y, t.x);
            uint32_t w1 = cvt_h2(t.w, t.z);
            *(uint2*)(kv_u + kk2 * V_PITCH_W + 2 * c) = make_uint2(w0, w1);
        }
    }
    __syncthreads();

    // ---- phase 3: exp into registers, partial sums -------------------------
    const int qe = tid & 15;
    const int ks = tid >> 4;
    float e[16];
    {
        const float m = m_s[qe];
        float s = 0.f;
#pragma unroll
        for (int kk = 0; kk < 16; kk++) {
            const int k = ks * 16 + kk;
            const float ev = ex2_fast((s_s[k * 17 + qe] - m) * LOG2E);
            e[kk] = ev;
            s += ev;
        }
        psum[qe * 17 + ks] = s;
    }
    __syncthreads();
    if (tid < 16) {
        float l = psum[tid * 17];
#pragma unroll
        for (int i = 1; i < 16; i++) l += psum[tid * 17 + i];
        r_s[tid] = 1.0f / l;
    }
    __syncthreads();

    // ---- phase 4: write attn (from regs) + p_h f16 (overlays s_s) ---------
    {
        const float r = r_s[qe];
        float4* ab = (float4*)(attn_out + (size_t)(bh * LQ_ + qt * 16 + qe) * LK_
                               + ks * 16);
#pragma unroll
        for (int j = 0; j < 4; j++)
            ab[j] = make_float4(e[4*j] * r, e[4*j+1] * r, e[4*j+2] * r, e[4*j+3] * r);
#pragma unroll
        for (int j = 0; j < 8; j++)
            ph_u[qe * P_PITCH_W + ks * 8 + j] = cvt_h2(e[2*j+1] * r, e[2*j] * r);
    }
    __syncthreads();

    // ---- phase 5: epilogue GEMM out[16q x 64d] = p[16x256] @ v[256x64] ----
    {
        const int d0 = wid * 8;
        float c0 = 0.f, c1 = 0.f, c2 = 0.f, c3 = 0.f;
        const uint32_t pa_base = smem_u32(ph_u) + ((lane & 15) * P_PITCH_W) * 4;
        const uint32_t vb_base = smem_u32(kv_u) + ((lane & 15) * V_PITCH_W + (d0 >> 1)) * 4;
#pragma unroll
        for (int kb = 0; kb < 16; kb++) {
            uint32_t a0, a1, a2, a3, b0, b1;
            const uint32_t pa = pa_base + (kb * 8 + (lane >> 4) * 4) * 4;
            asm volatile("ldmatrix.sync.aligned.m8n8.x4.shared.b16 {%0,%1,%2,%3}, [%4];"
                         : "=r"(a0), "=r"(a1), "=r"(a2), "=r"(a3) : "r"(pa));
            const uint32_t vb = vb_base + (kb * 16 * V_PITCH_W) * 4;
            asm volatile("ldmatrix.sync.aligned.m8n8.x2.trans.shared.b16 {%0,%1}, [%2];"
                         : "=r"(b0), "=r"(b1) : "r"(vb));
            mma16816(c0, c1, c2, c3, a0, a1, a2, a3, b0, b1);
        }
        const int qr = lane >> 2;
        const int dc = d0 + 2 * (lane & 3);
        float* ob = out + (size_t)(bh * LQ_ + qt * 16) * DK_;
        *(float2*)(ob + qr * DK_ + dc)       = make_float2(c0, c1);
        *(float2*)(ob + (qr + 8) * DK_ + dc) = make_float2(c2, c3);
    }
}

// ---------------------------------------------------------------------------
extern "C" void kernel_launch(void* const* d_in, const int* in_sizes, int n_in,
                              void* d_out, int out_size)
{
    const float* q    = (const float*)d_in[0];
    const float* k    = (const float*)d_in[1];
    const float* v    = (const float*)d_in[2];
    const float* Wq_w = (const float*)d_in[3];
    const float* Wq_b = (const float*)d_in[4];
    const float* Wk_w = (const float*)d_in[5];
    const float* Wk_b = (const float*)d_in[6];
    const float* vs_w = (const float*)d_in[7];
    // vs_b (d_in[8]) is softmax-invariant: unused.

    float* out  = (float*)d_out;                            // [B,H,LQ,DK]
    float* attn = (float*)d_out + (size_t)BH_ * LQ_ * DK_;  // [B,H,LQ,LK]

    const int smem_bytes = SM_WORDS * 4;
    cudaFuncSetAttribute(attn_fused_kernel,
                         cudaFuncAttributeMaxDynamicSharedMemorySize, smem_bytes);

    attn_fused_kernel<<<512, 256, smem_bytes>>>(q, k, v, Wq_w, Wq_b, Wk_w, Wk_b,
                                                vs_w, out, attn);
}

// round 15
// speedup vs baseline: 1.2216x; 1.2216x over previous
#include <cuda_runtime.h>
#include <cuda_bf16.h>
#include <cstdint>

#define B_  4
#define H_  8
#define LQ_ 256
#define LK_ 256
#define DK_ 64
#define BH_ (B_*H_)                 // 32
#define LOG2E 1.4426950408889634f

// kp f16x2 words: row r (0..8191), 32 words (64 dims). 1 MB.
__device__ uint32_t g_kp[(size_t)BH_ * LK_ * 32];
// per-bh ticket counters, padded to 128B stride. Monotonic across launches.
__device__ unsigned g_cnt[BH_ * 32];

// ---------------- packed-math helpers -------------------------------------
// f16x2 pack: first PTX operand -> HIGH half
__device__ __forceinline__ uint32_t cvt_h2(float hi, float lo) {
    uint32_t r; asm("cvt.rn.f16x2.f32 %0,%1,%2;" : "=r"(r) : "f"(hi), "f"(lo)); return r;
}
__device__ __forceinline__ uint32_t hadd2(uint32_t a, uint32_t b) {
    uint32_t r; asm("add.rn.f16x2 %0,%1,%2;" : "=r"(r) : "r"(a), "r"(b)); return r;
}
__device__ __forceinline__ uint32_t hfma2(uint32_t a, uint32_t b, uint32_t c) {
    uint32_t r; asm("fma.rn.f16x2 %0,%1,%2,%3;" : "=r"(r) : "r"(a), "r"(b), "r"(c)); return r;
}
__device__ __forceinline__ uint32_t tanh2(uint32_t x) {
    uint32_t y; asm("tanh.approx.f16x2 %0,%1;" : "=r"(y) : "r"(x)); return y;
}
__device__ __forceinline__ void h2tof(uint32_t h, float& lo, float& hi) {
    asm("{.reg .b16 l,h; mov.b32 {l,h},%2; cvt.f32.f16 %0,l; cvt.f32.f16 %1,h;}"
        : "=f"(lo), "=f"(hi) : "r"(h));
}
__device__ __forceinline__ float ex2_fast(float x) {
    float y; asm("ex2.approx.f32 %0,%1;" : "=f"(y) : "f"(x)); return y;
}
__device__ __forceinline__ uint32_t smem_u32(const void* p) {
    return (uint32_t)__cvta_generic_to_shared(p);
}
__device__ __forceinline__ void mma16816(float& c0, float& c1, float& c2, float& c3,
                                         uint32_t a0, uint32_t a1, uint32_t a2, uint32_t a3,
                                         uint32_t b0, uint32_t b1) {
    asm volatile("mma.sync.aligned.m16n8k16.row.col.f32.f16.f16.f32 "
                 "{%0,%1,%2,%3},{%4,%5,%6,%7},{%8,%9},{%0,%1,%2,%3};"
                 : "+f"(c0), "+f"(c1), "+f"(c2), "+f"(c3)
                 : "r"(a0), "r"(a1), "r"(a2), "r"(a3), "r"(b0), "r"(b1));
}

// ---------------------------------------------------------------------------
// ONE fused kernel. grid = 512 CTAs (32 bh x 16 q-tiles of 16 rows),
// 256 thr, 4 CTAs/SM (single wave -> device barrier is safe).
// Proj: each CTA projects its own 16 q rows (-> smem) and 16 distinct k rows
// (-> g_kp), then a per-bh ticket barrier; attn body identical to R9.
// ---------------------------------------------------------------------------
// smem layout (u32 word indices) — 56704 B, same as R9
#define SM_KV    0        // 9216: kp f16x2 pitch 32; later v f16 pitch 36
#define SM_W2H   9216     // 32
#define SM_S     9248     // 4352 f32 scores pitch 17; later p_h f16 pitch 264
#define SM_PMAX  13600    // 16 x 17  (overlaid by qp_tmp 512 w during proj/scores)
#define SM_PSUM  13872    // 16 x 17
#define SM_M     14144    // 16
#define SM_R     14160    // 16
#define SM_WORDS 14176    // 56704 bytes

#define SM_QPT   13600    // qp_tmp: 16 rows x 32 words (dead before pmax written)

#define P_PITCH_W 132     // p_h pitch in u32 words (264 f16, 528B)
#define V_PITCH_W 36      // v_h pitch in u32 words (72 f16, 144B)

__global__ __launch_bounds__(256, 4) void attn_fused_kernel(
    const float* __restrict__ qg,
    const float* __restrict__ kg,
    const float* __restrict__ v,
    const float* __restrict__ Wq, const float* __restrict__ bq,
    const float* __restrict__ Wk, const float* __restrict__ bk,
    const float* __restrict__ vs_w,
    float* __restrict__ out,        // [BH,256,64]
    float* __restrict__ attn_out)   // [BH,256,256]
{
    extern __shared__ float sm[];
    uint32_t* kv_u   = (uint32_t*)sm + SM_KV;
    uint32_t* w2h_s  = (uint32_t*)sm + SM_W2H;
    float*    s_s    = sm + SM_S;
    uint32_t* ph_u   = (uint32_t*)sm + SM_S;    // overlays s_s after scores die
    uint32_t* qp_tmp = (uint32_t*)sm + SM_QPT;  // proj+scores phases only
    float* pmax = sm + SM_PMAX;
    float* psum = sm + SM_PSUM;
    float* m_s  = sm + SM_M;
    float* r_s  = sm + SM_R;

    const int tid  = threadIdx.x;
    const int wid  = tid >> 5;
    const int lane = tid & 31;
    const int bh   = blockIdx.x >> 4;
    const int qt   = blockIdx.x & 15;

    // ============ phase P: non-redundant projections =======================
    // warps 0-3: qp of this CTA's 16 q rows, n-cols [16w,16w+16) -> qp_tmp
    // warps 4-7: kp of k rows [16qt,16qt+16), n-cols [16(w-4),..) -> g_kp
    {
        const int lr = lane >> 2;          // 0..7
        const int lc = 2 * (lane & 3);     // 0,2,4,6
        const bool isQ = (wid < 4);
        const int nw = wid & 3;
        const float* xbase = isQ ? (qg + (size_t)(bh * LQ_ + qt * 16) * DK_)
                                 : (kg + (size_t)(bh * LK_ + qt * 16) * DK_);
        const float* W    = isQ ? Wq : Wk;
        const float* bias = isQ ? bq : bk;

        uint32_t a[4][4];
#pragma unroll
        for (int ks = 0; ks < 4; ks++) {
            const int c = ks * 16 + lc;
            float2 t0 = *(const float2*)(xbase + lr * DK_ + c);
            float2 t1 = *(const float2*)(xbase + (lr + 8) * DK_ + c);
            float2 t2 = *(const float2*)(xbase + lr * DK_ + c + 8);
            float2 t3 = *(const float2*)(xbase + (lr + 8) * DK_ + c + 8);
            a[ks][0] = cvt_h2(t0.y, t0.x);
            a[ks][1] = cvt_h2(t1.y, t1.x);
            a[ks][2] = cvt_h2(t2.y, t2.x);
            a[ks][3] = cvt_h2(t3.y, t3.x);
        }
        uint32_t* gk = g_kp + (size_t)(bh * LK_ + qt * 16) * 32;
#pragma unroll
        for (int n2 = 0; n2 < 2; n2++) {
            const int n  = nw * 2 + n2;        // m16n8 tile, cols [8n,8n+8)
            const int nr = n * 8 + lr;         // W row (e-col)
            float c0 = 0.f, c1 = 0.f, c2 = 0.f, c3 = 0.f;
#pragma unroll
            for (int ks = 0; ks < 4; ks++) {
                const int k0 = ks * 16 + lc;
                float2 w0 = *(const float2*)(W + nr * DK_ + k0);
                float2 w1 = *(const float2*)(W + nr * DK_ + k0 + 8);
                mma16816(c0, c1, c2, c3, a[ks][0], a[ks][1], a[ks][2], a[ks][3],
                         cvt_h2(w0.y, w0.x), cvt_h2(w1.y, w1.x));
            }
            const int cb = n * 8 + lc;
            const float bl = bias[cb], bh2 = bias[cb + 1];
            const uint32_t wlo = cvt_h2(c1 + bh2, c0 + bl);
            const uint32_t whi = cvt_h2(c3 + bh2, c2 + bl);
            const int wi = n * 4 + (lane & 3);
            if (isQ) {
                qp_tmp[lr * 32 + wi]       = wlo;
                qp_tmp[(lr + 8) * 32 + wi] = whi;
            } else {
                gk[lr * 32 + wi]       = wlo;
                gk[(lr + 8) * 32 + wi] = whi;
            }
        }
    }
    if (tid < 32) w2h_s[tid] = cvt_h2(vs_w[2 * tid + 1], vs_w[2 * tid]);

    // ---- per-bh device barrier (16 CTAs; monotonic tickets, no reset) -----
    __threadfence();     // make this thread's g_kp stores GPU-visible
    __syncthreads();     // all threads' fences done before the atomic
    if (tid == 0) {
        const unsigned t = atomicAdd(&g_cnt[bh * 32], 1u);
        const unsigned target = (t & ~15u) + 16u;
        volatile unsigned* p = &g_cnt[bh * 32];
        while (*p < target) { __nanosleep(64); }
    }
    __syncthreads();

    // ============ phase 0: stage kp tile [256][32w] from g_kp ==============
    {
        const uint4* src = (const uint4*)(g_kp + (size_t)(bh * LK_) * 32);
        uint4* dst = (uint4*)kv_u;
#pragma unroll
        for (int i = 0; i < 8; i++) dst[tid + 256 * i] = src[tid + 256 * i];
    }
    __syncthreads();

    // ============ phase 1: scores (R9 body) ================================
    const int q    = lane & 15;
    const int kh   = lane >> 4;
    const int kbase2 = wid * 32 + kh * 16;
    float cm = -1e30f;

#pragma unroll 1
    for (int h = 0; h < 2; h++) {
        uint32_t qph[16], wh[16];
        {
            const uint4* qs = (const uint4*)(qp_tmp + q * 32 + h * 16);
#pragma unroll
            for (int j = 0; j < 4; j++) {
                uint4 t = qs[j];
                qph[4*j] = t.x; qph[4*j+1] = t.y; qph[4*j+2] = t.z; qph[4*j+3] = t.w;
            }
        }
#pragma unroll
        for (int j = 0; j < 16; j++) wh[j] = w2h_s[h * 16 + j];

        const uint4* kr = (const uint4*)(kv_u + kbase2 * 32 + h * 16);
        float* srow = s_s + kbase2 * 17 + q;
#pragma unroll 2
        for (int kk = 0; kk < 16; kk++, kr += 8, srow += 17) {
            const uint4 c0 = kr[0], c1 = kr[1], c2 = kr[2], c3 = kr[3];
            uint32_t h0 = 0, h1 = 0, g0 = 0, g1 = 0;
            h0 = hfma2(tanh2(hadd2(qph[0],  c0.x)), wh[0],  h0);
            h1 = hfma2(tanh2(hadd2(qph[1],  c0.y)), wh[1],  h1);
            h0 = hfma2(tanh2(hadd2(qph[2],  c0.z)), wh[2],  h0);
            h1 = hfma2(tanh2(hadd2(qph[3],  c0.w)), wh[3],  h1);
            h0 = hfma2(tanh2(hadd2(qph[4],  c1.x)), wh[4],  h0);
            h1 = hfma2(tanh2(hadd2(qph[5],  c1.y)), wh[5],  h1);
            h0 = hfma2(tanh2(hadd2(qph[6],  c1.z)), wh[6],  h0);
            h1 = hfma2(tanh2(hadd2(qph[7],  c1.w)), wh[7],  h1);
            g0 = hfma2(tanh2(hadd2(qph[8],  c2.x)), wh[8],  g0);
            g1 = hfma2(tanh2(hadd2(qph[9],  c2.y)), wh[9],  g1);
            g0 = hfma2(tanh2(hadd2(qph[10], c2.z)), wh[10], g0);
            g1 = hfma2(tanh2(hadd2(qph[11], c2.w)), wh[11], g1);
            g0 = hfma2(tanh2(hadd2(qph[12], c3.x)), wh[12], g0);
            g1 = hfma2(tanh2(hadd2(qph[13], c3.y)), wh[13], g1);
            g0 = hfma2(tanh2(hadd2(qph[14], c3.z)), wh[14], g0);
            g1 = hfma2(tanh2(hadd2(qph[15], c3.w)), wh[15], g1);
            const uint32_t hs = hadd2(h0, h1);
            const uint32_t gs = hadd2(g0, g1);
            float f0, f1, f2, f3;
            h2tof(hs, f0, f1); h2tof(gs, f2, f3);
            const float part = (f0 + f1) + (f2 + f3);

            if (h == 0) {
                *srow = part;
            } else {
                const float sc = *srow + part;
                *srow = sc;
                cm = fmaxf(cm, sc);
            }
        }
    }
    pmax[q * 17 + wid * 2 + kh] = cm;   // overlays qp_tmp (now dead)
    __syncthreads();

    // ---- phase 2: row max + stage v as f16 (pitch 72 f16, overwrites kp) --
    if (tid < 16) {
        float m = pmax[tid * 17];
#pragma unroll
        for (int i = 1; i < 16; i++) m = fmaxf(m, pmax[tid * 17 + i]);
        m_s[tid] = m;
    }
    {
        const float4* vsrc = (const float4*)(v + (size_t)bh * (LK_ * DK_));
#pragma unroll
        for (int i = 0; i < 16; i++) {
            const int idx = tid + 256 * i;           // 0..4095; k=idx>>4, c=idx&15
            float4 t = vsrc[idx];
            const int kk2 = idx >> 4, c = idx & 15;
            uint32_t w0 = cvt_h2(t.y, t.x);
            uint32_t w1 = cvt_h2(t.w, t.z);
            *(uint2*)(kv_u + kk2 * V_PITCH_W + 2 * c) = make_uint2(w0, w1);
        }
    }
    __syncthreads();

    // ---- phase 3: exp into registers, partial sums -------------------------
    const int qe = tid & 15;
    const int ks = tid >> 4;
    float e[16];
    {
        const float m = m_s[qe];
        float s = 0.f;
#pragma unroll
        for (int kk = 0; kk < 16; kk++) {
            const int k = ks * 16 + kk;
            const float ev = ex2_fast((s_s[k * 17 + qe] - m) * LOG2E);
            e[kk] = ev;
            s += ev;
        }
        psum[qe * 17 + ks] = s;
    }
    __syncthreads();
    if (tid < 16) {
        float l = psum[tid * 17];
#pragma unroll
        for (int i = 1; i < 16; i++) l += psum[tid * 17 + i];
        r_s[tid] = 1.0f / l;
    }
    __syncthreads();

    // ---- phase 4: write attn (from regs) + p_h f16 (overlays s_s) ---------
    {
        const float r = r_s[qe];
        float4* ab = (float4*)(attn_out + (size_t)(bh * LQ_ + qt * 16 + qe) * LK_
                               + ks * 16);
#pragma unroll
        for (int j = 0; j < 4; j++)
            ab[j] = make_float4(e[4*j] * r, e[4*j+1] * r, e[4*j+2] * r, e[4*j+3] * r);
#pragma unroll
        for (int j = 0; j < 8; j++)
            ph_u[qe * P_PITCH_W + ks * 8 + j] = cvt_h2(e[2*j+1] * r, e[2*j] * r);
    }
    __syncthreads();

    // ---- phase 5: epilogue GEMM out[16q x 64d] = p[16x256] @ v[256x64] ----
    {
        const int d0 = wid * 8;
        float c0 = 0.f, c1 = 0.f, c2 = 0.f, c3 = 0.f;
        const uint32_t pa_base = smem_u32(ph_u) + ((lane & 15) * P_PITCH_W) * 4;
        const uint32_t vb_base = smem_u32(kv_u) + ((lane & 15) * V_PITCH_W + (d0 >> 1)) * 4;
#pragma unroll
        for (int kb = 0; kb < 16; kb++) {
            uint32_t a0, a1, a2, a3, b0, b1;
            const uint32_t pa = pa_base + (kb * 8 + (lane >> 4) * 4) * 4;
            asm volatile("ldmatrix.sync.aligned.m8n8.x4.shared.b16 {%0,%1,%2,%3}, [%4];"
                         : "=r"(a0), "=r"(a1), "=r"(a2), "=r"(a3) : "r"(pa));
            const uint32_t vb = vb_base + (kb * 16 * V_PITCH_W) * 4;
            asm volatile("ldmatrix.sync.aligned.m8n8.x2.trans.shared.b16 {%0,%1}, [%2];"
                         : "=r"(b0), "=r"(b1) : "r"(vb));
            mma16816(c0, c1, c2, c3, a0, a1, a2, a3, b0, b1);
        }
        const int qr = lane >> 2;
        const int dc = d0 + 2 * (lane & 3);
        float* ob = out + (size_t)(bh * LQ_ + qt * 16) * DK_;
        *(float2*)(ob + qr * DK_ + dc)       = make_float2(c0, c1);
        *(float2*)(ob + (qr + 8) * DK_ + dc) = make_float2(c2, c3);
    }
}

// ---------------------------------------------------------------------------
extern "C" void kernel_launch(void* const* d_in, const int* in_sizes, int n_in,
                              void* d_out, int out_size)
{
    const float* q    = (const float*)d_in[0];
    const float* k    = (const float*)d_in[1];
    const float* v    = (const float*)d_in[2];
    const float* Wq_w = (const float*)d_in[3];
    const float* Wq_b = (const float*)d_in[4];
    const float* Wk_w = (const float*)d_in[5];
    const float* Wk_b = (const float*)d_in[6];
    const float* vs_w = (const float*)d_in[7];
    // vs_b (d_in[8]) is softmax-invariant: unused.

    float* out  = (float*)d_out;                            // [B,H,LQ,DK]
    float* attn = (float*)d_out + (size_t)BH_ * LQ_ * DK_;  // [B,H,LQ,LK]

    const int smem_bytes = SM_WORDS * 4;
    cudaFuncSetAttribute(attn_fused_kernel,
                         cudaFuncAttributeMaxDynamicSharedMemorySize, smem_bytes);

    attn_fused_kernel<<<512, 256, smem_bytes>>>(q, k, v, Wq_w, Wq_b, Wk_w, Wk_b,
                                                vs_w, out, attn);
}